// round 12
// baseline (speedup 1.0000x reference)
#include <cuda_runtime.h>
#include <cuda_bf16.h>
#include <math.h>
#include <stdint.h>

// Problem constants
#define BB 8
#define LL 4096
#define DD 1024
#define HH 16
#define HD 64
#define TT 64
#define D2 2048

// ---------------- scratch (device globals; no allocation) ----------------
__device__ float g_q[TT * DD];                          // projected query (fp32, attention input)
__device__ float g_kv[(size_t)BB * LL * D2];            // [B*L, 2048]: K | V (fp32)
__device__ float g_tmp[BB * TT * DD];                   // out_proj result (pre-LN)
__device__ float g_y[BB * TT * D2];                     // compressed @ w1^T + b1

// bf16 hi/lo operand planes
__device__ __nv_bfloat16 g_mem_h[(size_t)BB * LL * DD];
__device__ __nv_bfloat16 g_mem_l[(size_t)BB * LL * DD];
__device__ __nv_bfloat16 g_qry_h[TT * DD];
__device__ __nv_bfloat16 g_qry_l[TT * DD];
__device__ __nv_bfloat16 g_attn_h[BB * TT * DD];
__device__ __nv_bfloat16 g_attn_l[BB * TT * DD];
__device__ __nv_bfloat16 g_comp_h[BB * TT * DD];
__device__ __nv_bfloat16 g_comp_l[BB * TT * DD];
__device__ __nv_bfloat16 g_h_h[(size_t)BB * LL * D2];
__device__ __nv_bfloat16 g_h_l[(size_t)BB * LL * D2];
__device__ __nv_bfloat16 g_inw_h[3 * DD * DD];
__device__ __nv_bfloat16 g_inw_l[3 * DD * DD];
__device__ __nv_bfloat16 g_outw_h[DD * DD];
__device__ __nv_bfloat16 g_outw_l[DD * DD];
__device__ __nv_bfloat16 g_w1_h[D2 * DD];
__device__ __nv_bfloat16 g_w1_l[D2 * DD];
__device__ __nv_bfloat16 g_w2_h[DD * D2];
__device__ __nv_bfloat16 g_w2_l[DD * D2];

// ================= PTX primitives (baseline sm_80+, compiles for plain sm_103) =================
__device__ __forceinline__ uint32_t smem_u32(const void* p) {
    uint32_t a;
    asm("{ .reg .u64 t; cvta.to.shared.u64 t, %1; cvt.u32.u64 %0, t; }" : "=r"(a) : "l"(p));
    return a;
}
__device__ __forceinline__ void ldm_x4(uint32_t* r, uint32_t addr) {
    asm volatile("ldmatrix.sync.aligned.m8n8.x4.shared.b16 {%0,%1,%2,%3}, [%4];"
        : "=r"(r[0]), "=r"(r[1]), "=r"(r[2]), "=r"(r[3]) : "r"(addr));
}
__device__ __forceinline__ void mma_bf16(float* d, const uint32_t* a, const uint32_t* b) {
    asm volatile("mma.sync.aligned.m16n8k16.row.col.f32.bf16.bf16.f32 "
        "{%0,%1,%2,%3}, {%4,%5,%6,%7}, {%8,%9}, {%0,%1,%2,%3};"
        : "+f"(d[0]), "+f"(d[1]), "+f"(d[2]), "+f"(d[3])
        : "r"(a[0]), "r"(a[1]), "r"(a[2]), "r"(a[3]), "r"(b[0]), "r"(b[1]));
}
__device__ __forceinline__ void cp16(uint32_t dst, const void* src) {
    asm volatile("cp.async.cg.shared.global [%0], [%1], 16;" :: "r"(dst), "l"(src));
}
__device__ __forceinline__ void cp16z(uint32_t dst, const void* src, int sz) {
    asm volatile("cp.async.cg.shared.global [%0], [%1], 16, %2;" :: "r"(dst), "l"(src), "r"(sz));
}
#define CP_COMMIT() asm volatile("cp.async.commit_group;" ::: "memory")
#define CP_WAIT1()  asm volatile("cp.async.wait_group 1;" ::: "memory")

// split one float4 into hi/lo bf16 pairs (each uint32 = 2 bf16)
__device__ __forceinline__ void split_cvt(float4 v, uint2& hi, uint2& lo) {
    uint32_t h01, h23, l01, l23;
    asm("cvt.rn.bf16x2.f32 %0, %1, %2;" : "=r"(h01) : "f"(v.y), "f"(v.x));
    asm("cvt.rn.bf16x2.f32 %0, %1, %2;" : "=r"(h23) : "f"(v.w), "f"(v.z));
    float hx = __uint_as_float(h01 << 16);
    float hy = __uint_as_float(h01 & 0xFFFF0000u);
    float hz = __uint_as_float(h23 << 16);
    float hw = __uint_as_float(h23 & 0xFFFF0000u);
    asm("cvt.rn.bf16x2.f32 %0, %1, %2;" : "=r"(l01) : "f"(v.y - hy), "f"(v.x - hx));
    asm("cvt.rn.bf16x2.f32 %0, %1, %2;" : "=r"(l23) : "f"(v.w - hw), "f"(v.z - hz));
    hi = make_uint2(h01, h23);
    lo = make_uint2(l01, l23);
}

// ---------------- fp32 -> bf16 hi/lo split (pre-pass) ----------------
__global__ __launch_bounds__(256)
void split_kernel(const float4* __restrict__ x, uint2* __restrict__ hi,
                  uint2* __restrict__ lo, int n4) {
    int i = blockIdx.x * 256 + threadIdx.x;
    if (i < n4) {
        uint2 h, l;
        split_cvt(x[i], h, l);
        hi[i] = h;
        lo[i] = l;
    }
}

// ============ warp-MMA GEMM: C[M,N] = A[M,K] @ W[N,K]^T + bias[N] ============
// A/W given as pre-split bf16 hi/lo planes [rows, K] row-major.
// 3-term product (hh + lh + hl), fp32 accum -> rel err ~1.5e-5.
// 128x128 tile / CTA, 8 warps, warp tile 64x32. cp.async 3-stage pipeline, K-slab 32.
// N % 128 == 0, K % 32 == 0, nslab >= 2; M ragged (zfill + guarded epilogue).
#define KSLAB 32
#define SROWB 80                       // bytes per smem row (40 bf16) -> conflict-free ldmatrix
#define PLANE_B (128 * SROWB)          // 10240
#define STAGE_B (4 * PLANE_B)          // Ahi, Alo, Bhi, Blo = 40960
#define STAGES 3
#define GEMM_SMEM (STAGES * STAGE_B)   // 122880

__device__ __forceinline__ void issue_slab(
    uint32_t sbase,
    const __nv_bfloat16* __restrict__ Ah, const __nv_bfloat16* __restrict__ Al,
    const __nv_bfloat16* __restrict__ Wh, const __nv_bfloat16* __restrict__ Wl,
    int row0, int col0, int M, int K, int k0, int tid) {
    const int r = tid >> 2;            // 0..63
    const int q = tid & 3;             // 16B chunk within 32-col slab
    #pragma unroll
    for (int i = 0; i < 2; i++) {
        const int rr = r + 64 * i;
        const uint32_t off = (uint32_t)(rr * SROWB + q * 16);
        const size_t aoff = (size_t)(row0 + rr) * K + k0 + q * 8;
        const int asz = (row0 + rr < M) ? 16 : 0;
        cp16z(sbase + off,               Ah + aoff, asz);
        cp16z(sbase + PLANE_B + off,     Al + aoff, asz);
        const size_t boff = (size_t)(col0 + rr) * K + k0 + q * 8;
        cp16(sbase + 2 * PLANE_B + off,  Wh + boff);
        cp16(sbase + 3 * PLANE_B + off,  Wl + boff);
    }
}

__global__ __launch_bounds__(256, 1)
void gemm_mma_kernel(const __nv_bfloat16* __restrict__ Ah, const __nv_bfloat16* __restrict__ Al,
                     const __nv_bfloat16* __restrict__ Wh, const __nv_bfloat16* __restrict__ Wl,
                     const float* __restrict__ bias, float* __restrict__ C,
                     int M, int N, int K) {
    extern __shared__ char sm[];
    const uint32_t sb = smem_u32(sm);

    const int tid    = threadIdx.x;
    const int wid    = tid >> 5;
    const int lane   = tid & 31;
    const int warp_m = wid & 1;        // 0..1 -> 64-row halves
    const int warp_n = wid >> 1;       // 0..3 -> 32-col quarters
    const int row0   = blockIdx.y * 128;
    const int col0   = blockIdx.x * 128;

    float c[4][4][4];
    #pragma unroll
    for (int i = 0; i < 4; i++)
        #pragma unroll
        for (int j = 0; j < 4; j++)
            #pragma unroll
            for (int t = 0; t < 4; t++) c[i][j][t] = 0.f;

    const int nslab = K / KSLAB;

    // prologue: stages 0,1 in flight
    issue_slab(sb,           Ah, Al, Wh, Wl, row0, col0, M, K, 0,      tid);
    CP_COMMIT();
    issue_slab(sb + STAGE_B, Ah, Al, Wh, Wl, row0, col0, M, K, KSLAB, tid);
    CP_COMMIT();

    for (int s = 0; s < nslab; s++) {
        CP_WAIT1();                    // slab s resident (s+1 may still fly)
        __syncthreads();               // all warps past compute of s-1; its buffer is free

        if (s + 2 < nslab)
            issue_slab(sb + ((s + 2) % STAGES) * STAGE_B, Ah, Al, Wh, Wl,
                       row0, col0, M, K, (s + 2) * KSLAB, tid);
        CP_COMMIT();                   // always commit to keep group accounting uniform

        const uint32_t bbase = sb + (s % STAGES) * STAGE_B;

        #pragma unroll
        for (int ks = 0; ks < 2; ks++) {
            uint32_t ah[4][4], al[4][4], bh[2][4], bl[2][4];
            const int arow = warp_m * 64 + (lane & 15);
            const int akh  = lane >> 4;
            #pragma unroll
            for (int ma = 0; ma < 4; ma++) {
                uint32_t addr = bbase + (uint32_t)((arow + ma * 16) * SROWB + ks * 32 + akh * 16);
                ldm_x4(ah[ma], addr);
                ldm_x4(al[ma], addr + PLANE_B);
            }
            // B: W is [N,K] (K contig) == col-major B for mma.row.col -> NON-trans ldmatrix.
            const int bn  = warp_n * 32 + (lane & 7) + ((lane >> 4) << 3);
            const int bkh = (lane >> 3) & 1;
            #pragma unroll
            for (int p = 0; p < 2; p++) {
                uint32_t addr = bbase + 2 * PLANE_B
                              + (uint32_t)((bn + p * 16) * SROWB + ks * 32 + bkh * 16);
                ldm_x4(bh[p], addr);
                ldm_x4(bl[p], addr + PLANE_B);
            }
            #pragma unroll
            for (int ma = 0; ma < 4; ma++)
                #pragma unroll
                for (int na = 0; na < 4; na++) {
                    const uint32_t* bhp = &bh[na >> 1][(na & 1) * 2];
                    const uint32_t* blp = &bl[na >> 1][(na & 1) * 2];
                    mma_bf16(c[ma][na], ah[ma], bhp);   // hi*hi
                    mma_bf16(c[ma][na], al[ma], bhp);   // lo*hi
                    mma_bf16(c[ma][na], ah[ma], blp);   // hi*lo
                }
        }
    }

    // epilogue: fragment -> gmem with bias
    const int g  = lane >> 2;
    const int tg = lane & 3;
    #pragma unroll
    for (int ma = 0; ma < 4; ma++) {
        #pragma unroll
        for (int half = 0; half < 2; half++) {
            int r = row0 + warp_m * 64 + ma * 16 + g + half * 8;
            if (r < M) {
                float* cp = C + (size_t)r * N;
                #pragma unroll
                for (int na = 0; na < 4; na++) {
                    int cc = col0 + warp_n * 32 + na * 8 + tg * 2;
                    float2 o;
                    o.x = c[ma][na][half * 2 + 0] + bias[cc + 0];
                    o.y = c[ma][na][half * 2 + 1] + bias[cc + 1];
                    *(float2*)(cp + cc) = o;
                }
            }
        }
    }
}

// ---------------- flash attention: one CTA per (b,h); writes bf16 hi/lo ----------------
__global__ __launch_bounds__(256)
void flash_attn_kernel(const float* __restrict__ q, const float* __restrict__ kv,
                       __nv_bfloat16* __restrict__ attn_h, __nv_bfloat16* __restrict__ attn_l) {
    const int bh = blockIdx.x;
    const int b = bh / HH, h = bh % HH;

    __shared__ float Qs[64][68];
    __shared__ float Ks[32][68];
    __shared__ float Vs[32][68];
    __shared__ float Ps[64][36];

    const int tid = threadIdx.x;
    const int tx = tid & 7;
    const int ty = tid >> 3;
    const int t0 = ty * 2, t1 = t0 + 1;

    {
        int r = tid >> 2;
        int cc = (tid & 3) * 16;
        const float* src = q + (size_t)r * DD + h * HD + cc;
        *(float4*)&Qs[r][cc]      = *(const float4*)(src);
        *(float4*)&Qs[r][cc + 4]  = *(const float4*)(src + 4);
        *(float4*)&Qs[r][cc + 8]  = *(const float4*)(src + 8);
        *(float4*)&Qs[r][cc + 12] = *(const float4*)(src + 12);
    }

    float m0 = -3.402823466e38f, m1 = -3.402823466e38f;
    float l0s = 0.f, l1s = 0.f;
    float o0[8], o1[8];
    #pragma unroll
    for (int j = 0; j < 8; j++) { o0[j] = 0.f; o1[j] = 0.f; }

    for (int lb = 0; lb < LL; lb += 32) {
        {
            int r = tid >> 3;
            int cc = (tid & 7) * 8;
            const float* kp = kv + (size_t)(b * LL + lb + r) * D2 + h * HD + cc;
            *(float4*)&Ks[r][cc]     = *(const float4*)kp;
            *(float4*)&Ks[r][cc + 4] = *(const float4*)(kp + 4);
            const float* vp = kp + DD;
            *(float4*)&Vs[r][cc]     = *(const float4*)vp;
            *(float4*)&Vs[r][cc + 4] = *(const float4*)(vp + 4);
        }
        __syncthreads();

        float s0[4] = {0.f, 0.f, 0.f, 0.f};
        float s1[4] = {0.f, 0.f, 0.f, 0.f};
        #pragma unroll 8
        for (int d = 0; d < 64; d++) {
            float a0 = Qs[t0][d];
            float a1 = Qs[t1][d];
            #pragma unroll
            for (int j = 0; j < 4; j++) {
                float kk = Ks[tx * 4 + j][d];
                s0[j] = fmaf(a0, kk, s0[j]);
                s1[j] = fmaf(a1, kk, s1[j]);
            }
        }
        #pragma unroll
        for (int j = 0; j < 4; j++) { s0[j] *= 0.125f; s1[j] *= 0.125f; }

        float rm0 = fmaxf(fmaxf(s0[0], s0[1]), fmaxf(s0[2], s0[3]));
        float rm1 = fmaxf(fmaxf(s1[0], s1[1]), fmaxf(s1[2], s1[3]));
        #pragma unroll
        for (int off = 1; off < 8; off <<= 1) {
            rm0 = fmaxf(rm0, __shfl_xor_sync(0xffffffffu, rm0, off));
            rm1 = fmaxf(rm1, __shfl_xor_sync(0xffffffffu, rm1, off));
        }
        float mn0 = fmaxf(m0, rm0), mn1 = fmaxf(m1, rm1);
        float c0 = __expf(m0 - mn0), c1 = __expf(m1 - mn1);

        float p0[4], p1[4];
        float rs0 = 0.f, rs1 = 0.f;
        #pragma unroll
        for (int j = 0; j < 4; j++) {
            p0[j] = __expf(s0[j] - mn0); rs0 += p0[j];
            p1[j] = __expf(s1[j] - mn1); rs1 += p1[j];
        }
        #pragma unroll
        for (int off = 1; off < 8; off <<= 1) {
            rs0 += __shfl_xor_sync(0xffffffffu, rs0, off);
            rs1 += __shfl_xor_sync(0xffffffffu, rs1, off);
        }
        l0s = l0s * c0 + rs0;
        l1s = l1s * c1 + rs1;
        m0 = mn0; m1 = mn1;
        #pragma unroll
        for (int j = 0; j < 8; j++) { o0[j] *= c0; o1[j] *= c1; }

        #pragma unroll
        for (int j = 0; j < 4; j++) {
            Ps[t0][tx * 4 + j] = p0[j];
            Ps[t1][tx * 4 + j] = p1[j];
        }
        __syncthreads();

        #pragma unroll 4
        for (int lc = 0; lc < 32; lc++) {
            float pv0 = Ps[t0][lc];
            float pv1 = Ps[t1][lc];
            #pragma unroll
            for (int j = 0; j < 8; j++) {
                float vv = Vs[lc][tx * 8 + j];
                o0[j] = fmaf(pv0, vv, o0[j]);
                o1[j] = fmaf(pv1, vv, o1[j]);
            }
        }
        __syncthreads();
    }

    float inv0 = 1.f / l0s, inv1 = 1.f / l1s;
    size_t base0 = (size_t)(b * TT + t0) * DD + h * HD + tx * 8;
    size_t base1 = (size_t)(b * TT + t1) * DD + h * HD + tx * 8;
    #pragma unroll
    for (int j = 0; j < 8; j++) {
        float v0 = o0[j] * inv0;
        float v1 = o1[j] * inv1;
        __nv_bfloat16 h0 = __float2bfloat16(v0);
        __nv_bfloat16 h1 = __float2bfloat16(v1);
        attn_h[base0 + j] = h0;
        attn_l[base0 + j] = __float2bfloat16(v0 - __bfloat162float(h0));
        attn_h[base1 + j] = h1;
        attn_l[base1 + j] = __float2bfloat16(v1 - __bfloat162float(h1));
    }
}

// ---------------- LayerNorm (1024) -> fp32 out + bf16 hi/lo planes ----------------
__global__ __launch_bounds__(256)
void ln_kernel(const float* __restrict__ x, const float* __restrict__ gam,
               const float* __restrict__ bet, float* __restrict__ out,
               uint2* __restrict__ comp_h, uint2* __restrict__ comp_l) {
    const int row = blockIdx.x;
    const int tid = threadIdx.x;
    const float4* xr = (const float4*)(x + (size_t)row * DD);
    float4 v = xr[tid];
    float s  = v.x + v.y + v.z + v.w;
    float sq = v.x * v.x + v.y * v.y + v.z * v.z + v.w * v.w;
    #pragma unroll
    for (int off = 16; off > 0; off >>= 1) {
        s  += __shfl_xor_sync(0xffffffffu, s, off);
        sq += __shfl_xor_sync(0xffffffffu, sq, off);
    }
    __shared__ float ss[8], ssq[8];
    int w = tid >> 5, ln = tid & 31;
    if (ln == 0) { ss[w] = s; ssq[w] = sq; }
    __syncthreads();
    if (tid < 32) {
        float a = (tid < 8) ? ss[tid] : 0.f;
        float bq = (tid < 8) ? ssq[tid] : 0.f;
        #pragma unroll
        for (int off = 4; off > 0; off >>= 1) {
            a  += __shfl_xor_sync(0xffffffffu, a, off);
            bq += __shfl_xor_sync(0xffffffffu, bq, off);
        }
        if (tid == 0) { ss[0] = a; ssq[0] = bq; }
    }
    __syncthreads();
    float mu  = ss[0] * (1.f / 1024.f);
    float var = ssq[0] * (1.f / 1024.f) - mu * mu;
    float rstd = rsqrtf(var + 1e-5f);
    float4 gg = ((const float4*)gam)[tid];
    float4 bb = ((const float4*)bet)[tid];
    float4 o;
    o.x = (v.x - mu) * rstd * gg.x + bb.x;
    o.y = (v.y - mu) * rstd * gg.y + bb.y;
    o.z = (v.z - mu) * rstd * gg.z + bb.z;
    o.w = (v.w - mu) * rstd * gg.w + bb.w;
    ((float4*)(out + (size_t)row * DD))[tid] = o;
    uint2 hi, lo;
    split_cvt(o, hi, lo);
    comp_h[(size_t)row * (DD / 4) + tid] = hi;
    comp_l[(size_t)row * (DD / 4) + tid] = lo;
}

// ---------------- interp(y, T->L) + exact GELU -> bf16 hi/lo planes ----------------
__device__ __forceinline__ float gelu_exact(float x) {
    return 0.5f * x * (1.f + erff(x * 0.70710678118654752f));
}

__global__ __launch_bounds__(256)
void interp_gelu_kernel(const float* __restrict__ y,
                        uint2* __restrict__ h_h, uint2* __restrict__ h_l) {
    const int bl = blockIdx.x;
    const int b = bl >> 12;
    const int l = bl & 4095;
    float pos = ((float)l + 0.5f) * (64.f / 4096.f) - 0.5f;
    pos = fminf(fmaxf(pos, 0.f), 63.f);
    int i0 = (int)floorf(pos);
    int i1 = min(i0 + 1, 63);
    float f = pos - (float)i0;

    const float4* y0 = (const float4*)(y + (size_t)(b * TT + i0) * D2);
    const float4* y1 = (const float4*)(y + (size_t)(b * TT + i1) * D2);
    const size_t rowbase = (size_t)bl * (D2 / 4);
    const int tid = threadIdx.x;
    #pragma unroll
    for (int i = 0; i < 2; i++) {
        int idx = tid + i * 256;
        float4 a = y0[idx];
        float4 cv = y1[idx];
        float4 r;
        r.x = gelu_exact(a.x + f * (cv.x - a.x));
        r.y = gelu_exact(a.y + f * (cv.y - a.y));
        r.z = gelu_exact(a.z + f * (cv.z - a.z));
        r.w = gelu_exact(a.w + f * (cv.w - a.w));
        uint2 hi, lo;
        split_cvt(r, hi, lo);
        h_h[rowbase + idx] = hi;
        h_l[rowbase + idx] = lo;
    }
}

// ---------------- launch ----------------
extern "C" void kernel_launch(void* const* d_in, const int* in_sizes, int n_in,
                              void* d_out, int out_size) {
    const float* memory  = (const float*)d_in[0];   // [B,L,D]
    const float* query   = (const float*)d_in[1];   // [1,T,D]
    const float* in_w    = (const float*)d_in[2];   // [3D,D]
    const float* in_b    = (const float*)d_in[3];   // [3D]
    const float* out_w   = (const float*)d_in[4];   // [D,D]
    const float* out_b   = (const float*)d_in[5];   // [D]
    const float* lng     = (const float*)d_in[6];   // [D]
    const float* lnb     = (const float*)d_in[7];   // [D]
    const float* w1      = (const float*)d_in[8];   // [2D,D]
    const float* b1      = (const float*)d_in[9];   // [2D]
    const float* w2      = (const float*)d_in[10];  // [D,2D]
    const float* b2      = (const float*)d_in[11];  // [D]

    float* out = (float*)d_out;
    float* comp_out  = out;                          // [B,T,D]
    float* recon_out = out + (size_t)BB * TT * DD;   // [B,L,D]

    float *pq, *pkv, *ptmp, *py;
    __nv_bfloat16 *pmh, *pml, *pqh, *pql, *pah, *pal, *pch, *pcl, *phh, *phl;
    __nv_bfloat16 *piwh, *piwl, *powh, *powl, *pw1h, *pw1l, *pw2h, *pw2l;
    cudaGetSymbolAddress((void**)&pq,   g_q);
    cudaGetSymbolAddress((void**)&pkv,  g_kv);
    cudaGetSymbolAddress((void**)&ptmp, g_tmp);
    cudaGetSymbolAddress((void**)&py,   g_y);
    cudaGetSymbolAddress((void**)&pmh,  g_mem_h);
    cudaGetSymbolAddress((void**)&pml,  g_mem_l);
    cudaGetSymbolAddress((void**)&pqh,  g_qry_h);
    cudaGetSymbolAddress((void**)&pql,  g_qry_l);
    cudaGetSymbolAddress((void**)&pah,  g_attn_h);
    cudaGetSymbolAddress((void**)&pal,  g_attn_l);
    cudaGetSymbolAddress((void**)&pch,  g_comp_h);
    cudaGetSymbolAddress((void**)&pcl,  g_comp_l);
    cudaGetSymbolAddress((void**)&phh,  g_h_h);
    cudaGetSymbolAddress((void**)&phl,  g_h_l);
    cudaGetSymbolAddress((void**)&piwh, g_inw_h);
    cudaGetSymbolAddress((void**)&piwl, g_inw_l);
    cudaGetSymbolAddress((void**)&powh, g_outw_h);
    cudaGetSymbolAddress((void**)&powl, g_outw_l);
    cudaGetSymbolAddress((void**)&pw1h, g_w1_h);
    cudaGetSymbolAddress((void**)&pw1l, g_w1_l);
    cudaGetSymbolAddress((void**)&pw2h, g_w2_h);
    cudaGetSymbolAddress((void**)&pw2l, g_w2_l);

    cudaFuncSetAttribute(gemm_mma_kernel,
                         cudaFuncAttributeMaxDynamicSharedMemorySize, GEMM_SMEM);

    // ---- pre-split fp32 -> bf16 hi/lo ----
    split_kernel<<<(3 * DD * DD / 4 + 255) / 256, 256>>>((const float4*)in_w, (uint2*)piwh, (uint2*)piwl, 3 * DD * DD / 4);
    split_kernel<<<(DD * DD / 4 + 255) / 256, 256>>>((const float4*)out_w, (uint2*)powh, (uint2*)powl, DD * DD / 4);
    split_kernel<<<(D2 * DD / 4 + 255) / 256, 256>>>((const float4*)w1, (uint2*)pw1h, (uint2*)pw1l, D2 * DD / 4);
    split_kernel<<<(DD * D2 / 4 + 255) / 256, 256>>>((const float4*)w2, (uint2*)pw2h, (uint2*)pw2l, DD * D2 / 4);
    split_kernel<<<(TT * DD / 4 + 255) / 256, 256>>>((const float4*)query, (uint2*)pqh, (uint2*)pql, TT * DD / 4);
    {
        int n4 = (int)((size_t)BB * LL * DD / 4);
        split_kernel<<<(n4 + 255) / 256, 256>>>((const float4*)memory, (uint2*)pmh, (uint2*)pml, n4);
    }

    // 1) q = query @ Wq^T + bq             [64, 1024], K=1024
    gemm_mma_kernel<<<dim3(8, 1), 256, GEMM_SMEM>>>(pqh, pql, piwh, piwl, in_b, pq, TT, DD, DD);

    // 2) KV = memory @ [Wk;Wv]^T + [bk;bv] [32768, 2048], K=1024
    gemm_mma_kernel<<<dim3(16, 256), 256, GEMM_SMEM>>>(pmh, pml,
                                                       piwh + (size_t)DD * DD, piwl + (size_t)DD * DD,
                                                       in_b + DD, pkv, BB * LL, D2, DD);

    // 3) flash attention -> attn bf16 hi/lo
    flash_attn_kernel<<<BB * HH, 256>>>(pq, pkv, pah, pal);

    // 4) out_proj: g_tmp = attn @ out_w^T + out_b  [512, 1024], K=1024
    gemm_mma_kernel<<<dim3(8, 4), 256, GEMM_SMEM>>>(pah, pal, powh, powl, out_b, ptmp,
                                                    BB * TT, DD, DD);

    // 5) LayerNorm -> compressed (d_out) + bf16 hi/lo planes
    ln_kernel<<<BB * TT, 256>>>(ptmp, lng, lnb, comp_out, (uint2*)pch, (uint2*)pcl);

    // 6) y = compressed @ w1^T + b1  [512, 2048], K=1024 (interp commutes with linear)
    gemm_mma_kernel<<<dim3(16, 4), 256, GEMM_SMEM>>>(pch, pcl, pw1h, pw1l, b1, py, BB * TT, D2, DD);

    // 7) h = gelu(interp(y)) -> bf16 hi/lo  [B,L,2048]
    interp_gelu_kernel<<<BB * LL, 256>>>(py, (uint2*)phh, (uint2*)phl);

    // 8) recon = h @ w2^T + b2  [32768, 1024], K=2048 -> d_out tail
    gemm_mma_kernel<<<dim3(8, 256), 256, GEMM_SMEM>>>(phh, phl, pw2h, pw2l, b2, recon_out,
                                                      BB * LL, DD, D2);
}

// round 16
// speedup vs baseline: 1.0027x; 1.0027x over previous
#include <cuda_runtime.h>
#include <cuda_bf16.h>
#include <math.h>
#include <stdint.h>

// Problem constants
#define BB 8
#define LL 4096
#define DD 1024
#define HH 16
#define HD 64
#define TT 64
#define D2 2048

// ---------------- scratch (device globals; no allocation) ----------------
__device__ float g_q[TT * DD];                          // projected query (fp32, attention input)
__device__ float g_kv[(size_t)BB * LL * D2];            // [B*L, 2048]: K | V (fp32)
__device__ float g_tmp[BB * TT * DD];                   // out_proj result (pre-LN)
__device__ float g_y[BB * TT * D2];                     // compressed @ w1^T + b1

// bf16 hi/lo operand planes
__device__ __nv_bfloat16 g_mem_h[(size_t)BB * LL * DD];
__device__ __nv_bfloat16 g_mem_l[(size_t)BB * LL * DD];
__device__ __nv_bfloat16 g_qry_h[TT * DD];
__device__ __nv_bfloat16 g_qry_l[TT * DD];
__device__ __nv_bfloat16 g_attn_h[BB * TT * DD];
__device__ __nv_bfloat16 g_attn_l[BB * TT * DD];
__device__ __nv_bfloat16 g_comp_h[BB * TT * DD];
__device__ __nv_bfloat16 g_comp_l[BB * TT * DD];
__device__ __nv_bfloat16 g_h_h[(size_t)BB * LL * D2];
__device__ __nv_bfloat16 g_h_l[(size_t)BB * LL * D2];
__device__ __nv_bfloat16 g_inw_h[3 * DD * DD];
__device__ __nv_bfloat16 g_inw_l[3 * DD * DD];
__device__ __nv_bfloat16 g_outw_h[DD * DD];
__device__ __nv_bfloat16 g_outw_l[DD * DD];
__device__ __nv_bfloat16 g_w1_h[D2 * DD];
__device__ __nv_bfloat16 g_w1_l[D2 * DD];
__device__ __nv_bfloat16 g_w2_h[DD * D2];
__device__ __nv_bfloat16 g_w2_l[DD * D2];

// ================= PTX primitives (baseline sm_80+, compiles for plain sm_103) =================
__device__ __forceinline__ uint32_t smem_u32(const void* p) {
    uint32_t a;
    asm("{ .reg .u64 t; cvta.to.shared.u64 t, %1; cvt.u32.u64 %0, t; }" : "=r"(a) : "l"(p));
    return a;
}
__device__ __forceinline__ void ldm_x4(uint32_t* r, uint32_t addr) {
    asm volatile("ldmatrix.sync.aligned.m8n8.x4.shared.b16 {%0,%1,%2,%3}, [%4];"
        : "=r"(r[0]), "=r"(r[1]), "=r"(r[2]), "=r"(r[3]) : "r"(addr));
}
__device__ __forceinline__ void mma_bf16(float* d, const uint32_t* a, const uint32_t* b) {
    asm volatile("mma.sync.aligned.m16n8k16.row.col.f32.bf16.bf16.f32 "
        "{%0,%1,%2,%3}, {%4,%5,%6,%7}, {%8,%9}, {%0,%1,%2,%3};"
        : "+f"(d[0]), "+f"(d[1]), "+f"(d[2]), "+f"(d[3])
        : "r"(a[0]), "r"(a[1]), "r"(a[2]), "r"(a[3]), "r"(b[0]), "r"(b[1]));
}
__device__ __forceinline__ void cp16(uint32_t dst, const void* src) {
    asm volatile("cp.async.cg.shared.global [%0], [%1], 16;" :: "r"(dst), "l"(src));
}
__device__ __forceinline__ void cp16z(uint32_t dst, const void* src, int sz) {
    asm volatile("cp.async.cg.shared.global [%0], [%1], 16, %2;" :: "r"(dst), "l"(src), "r"(sz));
}
#define CP_COMMIT() asm volatile("cp.async.commit_group;" ::: "memory")
#define CP_WAIT1()  asm volatile("cp.async.wait_group 1;" ::: "memory")

// split one float4 into hi/lo bf16 pairs (each uint32 = 2 bf16)
__device__ __forceinline__ void split_cvt(float4 v, uint2& hi, uint2& lo) {
    uint32_t h01, h23, l01, l23;
    asm("cvt.rn.bf16x2.f32 %0, %1, %2;" : "=r"(h01) : "f"(v.y), "f"(v.x));
    asm("cvt.rn.bf16x2.f32 %0, %1, %2;" : "=r"(h23) : "f"(v.w), "f"(v.z));
    float hx = __uint_as_float(h01 << 16);
    float hy = __uint_as_float(h01 & 0xFFFF0000u);
    float hz = __uint_as_float(h23 << 16);
    float hw = __uint_as_float(h23 & 0xFFFF0000u);
    asm("cvt.rn.bf16x2.f32 %0, %1, %2;" : "=r"(l01) : "f"(v.y - hy), "f"(v.x - hx));
    asm("cvt.rn.bf16x2.f32 %0, %1, %2;" : "=r"(l23) : "f"(v.w - hw), "f"(v.z - hz));
    hi = make_uint2(h01, h23);
    lo = make_uint2(l01, l23);
}

// ---------------- fp32 -> bf16 hi/lo split (pre-pass) ----------------
__global__ __launch_bounds__(256)
void split_kernel(const float4* __restrict__ x, uint2* __restrict__ hi,
                  uint2* __restrict__ lo, int n4) {
    int i = blockIdx.x * 256 + threadIdx.x;
    if (i < n4) {
        uint2 h, l;
        split_cvt(x[i], h, l);
        hi[i] = h;
        lo[i] = l;
    }
}

// fused split for out_w (262144 f4) + w1 (524288 f4) + w2 (524288 f4)
#define OW4 (DD * DD / 4)
#define W14 (D2 * DD / 4)
#define W24 (DD * D2 / 4)
__global__ __launch_bounds__(256)
void split3_kernel(const float4* __restrict__ ow, uint2* __restrict__ owh, uint2* __restrict__ owl,
                   const float4* __restrict__ w1, uint2* __restrict__ w1h, uint2* __restrict__ w1l,
                   const float4* __restrict__ w2, uint2* __restrict__ w2h, uint2* __restrict__ w2l) {
    int i = blockIdx.x * 256 + threadIdx.x;
    const float4* src; uint2 *dh, *dl; int j;
    if (i < OW4)                { src = ow; dh = owh; dl = owl; j = i; }
    else if (i < OW4 + W14)     { src = w1; dh = w1h; dl = w1l; j = i - OW4; }
    else if (i < OW4 + W14 + W24) { src = w2; dh = w2h; dl = w2l; j = i - OW4 - W14; }
    else return;
    uint2 h, l;
    split_cvt(src[j], h, l);
    dh[j] = h;
    dl[j] = l;
}

// ============ warp-MMA GEMM: C[M,N] = A[M,K] @ W[N,K]^T + bias[N] ============
// A/W given as pre-split bf16 hi/lo planes [rows, K] row-major.
// 3-term product (hh + lh + hl), fp32 accum -> rel err ~1.5e-5.
// 128x128 tile / CTA, 8 warps, warp tile 64x32. cp.async 3-stage pipeline, K-slab 32.
// MMA issue is TERM-MAJOR: 16 independent accumulators between links of each
// dependent 3-chain (hh->lh->hl per accumulator) to kill RAW issue stalls.
// N % 128 == 0, K % 32 == 0, nslab >= 2; M ragged (zfill + guarded epilogue).
#define KSLAB 32
#define SROWB 80                       // bytes per smem row (40 bf16) -> conflict-free ldmatrix
#define PLANE_B (128 * SROWB)          // 10240
#define STAGE_B (4 * PLANE_B)          // Ahi, Alo, Bhi, Blo = 40960
#define STAGES 3
#define GEMM_SMEM (STAGES * STAGE_B)   // 122880

__device__ __forceinline__ void issue_slab(
    uint32_t sbase,
    const __nv_bfloat16* __restrict__ Ah, const __nv_bfloat16* __restrict__ Al,
    const __nv_bfloat16* __restrict__ Wh, const __nv_bfloat16* __restrict__ Wl,
    int row0, int col0, int M, int K, int k0, int tid) {
    const int r = tid >> 2;            // 0..63
    const int q = tid & 3;             // 16B chunk within 32-col slab
    #pragma unroll
    for (int i = 0; i < 2; i++) {
        const int rr = r + 64 * i;
        const uint32_t off = (uint32_t)(rr * SROWB + q * 16);
        const size_t aoff = (size_t)(row0 + rr) * K + k0 + q * 8;
        const int asz = (row0 + rr < M) ? 16 : 0;
        cp16z(sbase + off,               Ah + aoff, asz);
        cp16z(sbase + PLANE_B + off,     Al + aoff, asz);
        const size_t boff = (size_t)(col0 + rr) * K + k0 + q * 8;
        cp16(sbase + 2 * PLANE_B + off,  Wh + boff);
        cp16(sbase + 3 * PLANE_B + off,  Wl + boff);
    }
}

__global__ __launch_bounds__(256, 1)
void gemm_mma_kernel(const __nv_bfloat16* __restrict__ Ah, const __nv_bfloat16* __restrict__ Al,
                     const __nv_bfloat16* __restrict__ Wh, const __nv_bfloat16* __restrict__ Wl,
                     const float* __restrict__ bias, float* __restrict__ C,
                     int M, int N, int K) {
    extern __shared__ char sm[];
    const uint32_t sb = smem_u32(sm);

    const int tid    = threadIdx.x;
    const int wid    = tid >> 5;
    const int lane   = tid & 31;
    const int warp_m = wid & 1;        // 0..1 -> 64-row halves
    const int warp_n = wid >> 1;       // 0..3 -> 32-col quarters
    const int row0   = blockIdx.y * 128;
    const int col0   = blockIdx.x * 128;

    float c[4][4][4];
    #pragma unroll
    for (int i = 0; i < 4; i++)
        #pragma unroll
        for (int j = 0; j < 4; j++)
            #pragma unroll
            for (int t = 0; t < 4; t++) c[i][j][t] = 0.f;

    const int nslab = K / KSLAB;

    // prologue: stages 0,1 in flight
    issue_slab(sb,           Ah, Al, Wh, Wl, row0, col0, M, K, 0,      tid);
    CP_COMMIT();
    issue_slab(sb + STAGE_B, Ah, Al, Wh, Wl, row0, col0, M, K, KSLAB, tid);
    CP_COMMIT();

    for (int s = 0; s < nslab; s++) {
        CP_WAIT1();                    // slab s resident (s+1 may still fly)
        __syncthreads();               // all warps past compute of s-1; its buffer is free

        if (s + 2 < nslab)
            issue_slab(sb + ((s + 2) % STAGES) * STAGE_B, Ah, Al, Wh, Wl,
                       row0, col0, M, K, (s + 2) * KSLAB, tid);
        CP_COMMIT();                   // always commit to keep group accounting uniform

        const uint32_t bbase = sb + (s % STAGES) * STAGE_B;

        #pragma unroll
        for (int ks = 0; ks < 2; ks++) {
            uint32_t ah[4][4], al[4][4], bh[2][4], bl[2][4];
            const int arow = warp_m * 64 + (lane & 15);
            const int akh  = lane >> 4;
            #pragma unroll
            for (int ma = 0; ma < 4; ma++) {
                uint32_t addr = bbase + (uint32_t)((arow + ma * 16) * SROWB + ks * 32 + akh * 16);
                ldm_x4(ah[ma], addr);
                ldm_x4(al[ma], addr + PLANE_B);
            }
            // B: W is [N,K] (K contig) == col-major B for mma.row.col -> NON-trans ldmatrix.
            const int bn  = warp_n * 32 + (lane & 7) + ((lane >> 4) << 3);
            const int bkh = (lane >> 3) & 1;
            #pragma unroll
            for (int p = 0; p < 2; p++) {
                uint32_t addr = bbase + 2 * PLANE_B
                              + (uint32_t)((bn + p * 16) * SROWB + ks * 32 + bkh * 16);
                ldm_x4(bh[p], addr);
                ldm_x4(bl[p], addr + PLANE_B);
            }
            // TERM-MAJOR issue: 16 independent MMAs between each accumulator's
            // chain links. Per-accumulator accumulation order (hh, lh, hl per
            // k-step) is unchanged -> numerics identical to the R5/R12 pass.
            #pragma unroll
            for (int ma = 0; ma < 4; ma++)
                #pragma unroll
                for (int na = 0; na < 4; na++)
                    mma_bf16(c[ma][na], ah[ma], &bh[na >> 1][(na & 1) * 2]);   // hi*hi
            #pragma unroll
            for (int ma = 0; ma < 4; ma++)
                #pragma unroll
                for (int na = 0; na < 4; na++)
                    mma_bf16(c[ma][na], al[ma], &bh[na >> 1][(na & 1) * 2]);   // lo*hi
            #pragma unroll
            for (int ma = 0; ma < 4; ma++)
                #pragma unroll
                for (int na = 0; na < 4; na++)
                    mma_bf16(c[ma][na], ah[ma], &bl[na >> 1][(na & 1) * 2]);   // hi*lo
        }
    }

    // epilogue: fragment -> gmem with bias
    const int g  = lane >> 2;
    const int tg = lane & 3;
    #pragma unroll
    for (int ma = 0; ma < 4; ma++) {
        #pragma unroll
        for (int half = 0; half < 2; half++) {
            int r = row0 + warp_m * 64 + ma * 16 + g + half * 8;
            if (r < M) {
                float* cp = C + (size_t)r * N;
                #pragma unroll
                for (int na = 0; na < 4; na++) {
                    int cc = col0 + warp_n * 32 + na * 8 + tg * 2;
                    float2 o;
                    o.x = c[ma][na][half * 2 + 0] + bias[cc + 0];
                    o.y = c[ma][na][half * 2 + 1] + bias[cc + 1];
                    *(float2*)(cp + cc) = o;
                }
            }
        }
    }
}

// ---------------- flash attention: one CTA per (b,h); writes bf16 hi/lo ----------------
__global__ __launch_bounds__(256)
void flash_attn_kernel(const float* __restrict__ q, const float* __restrict__ kv,
                       __nv_bfloat16* __restrict__ attn_h, __nv_bfloat16* __restrict__ attn_l) {
    const int bh = blockIdx.x;
    const int b = bh / HH, h = bh % HH;

    __shared__ float Qs[64][68];
    __shared__ float Ks[32][68];
    __shared__ float Vs[32][68];
    __shared__ float Ps[64][36];

    const int tid = threadIdx.x;
    const int tx = tid & 7;
    const int ty = tid >> 3;
    const int t0 = ty * 2, t1 = t0 + 1;

    {
        int r = tid >> 2;
        int cc = (tid & 3) * 16;
        const float* src = q + (size_t)r * DD + h * HD + cc;
        *(float4*)&Qs[r][cc]      = *(const float4*)(src);
        *(float4*)&Qs[r][cc + 4]  = *(const float4*)(src + 4);
        *(float4*)&Qs[r][cc + 8]  = *(const float4*)(src + 8);
        *(float4*)&Qs[r][cc + 12] = *(const float4*)(src + 12);
    }

    float m0 = -3.402823466e38f, m1 = -3.402823466e38f;
    float l0s = 0.f, l1s = 0.f;
    float o0[8], o1[8];
    #pragma unroll
    for (int j = 0; j < 8; j++) { o0[j] = 0.f; o1[j] = 0.f; }

    for (int lb = 0; lb < LL; lb += 32) {
        {
            int r = tid >> 3;
            int cc = (tid & 7) * 8;
            const float* kp = kv + (size_t)(b * LL + lb + r) * D2 + h * HD + cc;
            *(float4*)&Ks[r][cc]     = *(const float4*)kp;
            *(float4*)&Ks[r][cc + 4] = *(const float4*)(kp + 4);
            const float* vp = kp + DD;
            *(float4*)&Vs[r][cc]     = *(const float4*)vp;
            *(float4*)&Vs[r][cc + 4] = *(const float4*)(vp + 4);
        }
        __syncthreads();

        float s0[4] = {0.f, 0.f, 0.f, 0.f};
        float s1[4] = {0.f, 0.f, 0.f, 0.f};
        #pragma unroll 8
        for (int d = 0; d < 64; d++) {
            float a0 = Qs[t0][d];
            float a1 = Qs[t1][d];
            #pragma unroll
            for (int j = 0; j < 4; j++) {
                float kk = Ks[tx * 4 + j][d];
                s0[j] = fmaf(a0, kk, s0[j]);
                s1[j] = fmaf(a1, kk, s1[j]);
            }
        }
        #pragma unroll
        for (int j = 0; j < 4; j++) { s0[j] *= 0.125f; s1[j] *= 0.125f; }

        float rm0 = fmaxf(fmaxf(s0[0], s0[1]), fmaxf(s0[2], s0[3]));
        float rm1 = fmaxf(fmaxf(s1[0], s1[1]), fmaxf(s1[2], s1[3]));
        #pragma unroll
        for (int off = 1; off < 8; off <<= 1) {
            rm0 = fmaxf(rm0, __shfl_xor_sync(0xffffffffu, rm0, off));
            rm1 = fmaxf(rm1, __shfl_xor_sync(0xffffffffu, rm1, off));
        }
        float mn0 = fmaxf(m0, rm0), mn1 = fmaxf(m1, rm1);
        float c0 = __expf(m0 - mn0), c1 = __expf(m1 - mn1);

        float p0[4], p1[4];
        float rs0 = 0.f, rs1 = 0.f;
        #pragma unroll
        for (int j = 0; j < 4; j++) {
            p0[j] = __expf(s0[j] - mn0); rs0 += p0[j];
            p1[j] = __expf(s1[j] - mn1); rs1 += p1[j];
        }
        #pragma unroll
        for (int off = 1; off < 8; off <<= 1) {
            rs0 += __shfl_xor_sync(0xffffffffu, rs0, off);
            rs1 += __shfl_xor_sync(0xffffffffu, rs1, off);
        }
        l0s = l0s * c0 + rs0;
        l1s = l1s * c1 + rs1;
        m0 = mn0; m1 = mn1;
        #pragma unroll
        for (int j = 0; j < 8; j++) { o0[j] *= c0; o1[j] *= c1; }

        #pragma unroll
        for (int j = 0; j < 4; j++) {
            Ps[t0][tx * 4 + j] = p0[j];
            Ps[t1][tx * 4 + j] = p1[j];
        }
        __syncthreads();

        #pragma unroll 4
        for (int lc = 0; lc < 32; lc++) {
            float pv0 = Ps[t0][lc];
            float pv1 = Ps[t1][lc];
            #pragma unroll
            for (int j = 0; j < 8; j++) {
                float vv = Vs[lc][tx * 8 + j];
                o0[j] = fmaf(pv0, vv, o0[j]);
                o1[j] = fmaf(pv1, vv, o1[j]);
            }
        }
        __syncthreads();
    }

    float inv0 = 1.f / l0s, inv1 = 1.f / l1s;
    size_t base0 = (size_t)(b * TT + t0) * DD + h * HD + tx * 8;
    size_t base1 = (size_t)(b * TT + t1) * DD + h * HD + tx * 8;
    #pragma unroll
    for (int j = 0; j < 8; j++) {
        float v0 = o0[j] * inv0;
        float v1 = o1[j] * inv1;
        __nv_bfloat16 h0 = __float2bfloat16(v0);
        __nv_bfloat16 h1 = __float2bfloat16(v1);
        attn_h[base0 + j] = h0;
        attn_l[base0 + j] = __float2bfloat16(v0 - __bfloat162float(h0));
        attn_h[base1 + j] = h1;
        attn_l[base1 + j] = __float2bfloat16(v1 - __bfloat162float(h1));
    }
}

// ---------------- LayerNorm (1024) -> fp32 out + bf16 hi/lo planes ----------------
__global__ __launch_bounds__(256)
void ln_kernel(const float* __restrict__ x, const float* __restrict__ gam,
               const float* __restrict__ bet, float* __restrict__ out,
               uint2* __restrict__ comp_h, uint2* __restrict__ comp_l) {
    const int row = blockIdx.x;
    const int tid = threadIdx.x;
    const float4* xr = (const float4*)(x + (size_t)row * DD);
    float4 v = xr[tid];
    float s  = v.x + v.y + v.z + v.w;
    float sq = v.x * v.x + v.y * v.y + v.z * v.z + v.w * v.w;
    #pragma unroll
    for (int off = 16; off > 0; off >>= 1) {
        s  += __shfl_xor_sync(0xffffffffu, s, off);
        sq += __shfl_xor_sync(0xffffffffu, sq, off);
    }
    __shared__ float ss[8], ssq[8];
    int w = tid >> 5, ln = tid & 31;
    if (ln == 0) { ss[w] = s; ssq[w] = sq; }
    __syncthreads();
    if (tid < 32) {
        float a = (tid < 8) ? ss[tid] : 0.f;
        float bq = (tid < 8) ? ssq[tid] : 0.f;
        #pragma unroll
        for (int off = 4; off > 0; off >>= 1) {
            a  += __shfl_xor_sync(0xffffffffu, a, off);
            bq += __shfl_xor_sync(0xffffffffu, bq, off);
        }
        if (tid == 0) { ss[0] = a; ssq[0] = bq; }
    }
    __syncthreads();
    float mu  = ss[0] * (1.f / 1024.f);
    float var = ssq[0] * (1.f / 1024.f) - mu * mu;
    float rstd = rsqrtf(var + 1e-5f);
    float4 gg = ((const float4*)gam)[tid];
    float4 bb = ((const float4*)bet)[tid];
    float4 o;
    o.x = (v.x - mu) * rstd * gg.x + bb.x;
    o.y = (v.y - mu) * rstd * gg.y + bb.y;
    o.z = (v.z - mu) * rstd * gg.z + bb.z;
    o.w = (v.w - mu) * rstd * gg.w + bb.w;
    ((float4*)(out + (size_t)row * DD))[tid] = o;
    uint2 hi, lo;
    split_cvt(o, hi, lo);
    comp_h[(size_t)row * (DD / 4) + tid] = hi;
    comp_l[(size_t)row * (DD / 4) + tid] = lo;
}

// ---------------- interp(y, T->L) + exact GELU -> bf16 hi/lo planes ----------------
__device__ __forceinline__ float gelu_exact(float x) {
    return 0.5f * x * (1.f + erff(x * 0.70710678118654752f));
}

__global__ __launch_bounds__(256)
void interp_gelu_kernel(const float* __restrict__ y,
                        uint2* __restrict__ h_h, uint2* __restrict__ h_l) {
    const int bl = blockIdx.x;
    const int b = bl >> 12;
    const int l = bl & 4095;
    float pos = ((float)l + 0.5f) * (64.f / 4096.f) - 0.5f;
    pos = fminf(fmaxf(pos, 0.f), 63.f);
    int i0 = (int)floorf(pos);
    int i1 = min(i0 + 1, 63);
    float f = pos - (float)i0;

    const float4* y0 = (const float4*)(y + (size_t)(b * TT + i0) * D2);
    const float4* y1 = (const float4*)(y + (size_t)(b * TT + i1) * D2);
    const size_t rowbase = (size_t)bl * (D2 / 4);
    const int tid = threadIdx.x;
    #pragma unroll
    for (int i = 0; i < 2; i++) {
        int idx = tid + i * 256;
        float4 a = y0[idx];
        float4 cv = y1[idx];
        float4 r;
        r.x = gelu_exact(a.x + f * (cv.x - a.x));
        r.y = gelu_exact(a.y + f * (cv.y - a.y));
        r.z = gelu_exact(a.z + f * (cv.z - a.z));
        r.w = gelu_exact(a.w + f * (cv.w - a.w));
        uint2 hi, lo;
        split_cvt(r, hi, lo);
        h_h[rowbase + idx] = hi;
        h_l[rowbase + idx] = lo;
    }
}

// ---------------- launch ----------------
extern "C" void kernel_launch(void* const* d_in, const int* in_sizes, int n_in,
                              void* d_out, int out_size) {
    const float* memory  = (const float*)d_in[0];   // [B,L,D]
    const float* query   = (const float*)d_in[1];   // [1,T,D]
    const float* in_w    = (const float*)d_in[2];   // [3D,D]
    const float* in_b    = (const float*)d_in[3];   // [3D]
    const float* out_w   = (const float*)d_in[4];   // [D,D]
    const float* out_b   = (const float*)d_in[5];   // [D]
    const float* lng     = (const float*)d_in[6];   // [D]
    const float* lnb     = (const float*)d_in[7];   // [D]
    const float* w1      = (const float*)d_in[8];   // [2D,D]
    const float* b1      = (const float*)d_in[9];   // [2D]
    const float* w2      = (const float*)d_in[10];  // [D,2D]
    const float* b2      = (const float*)d_in[11];  // [D]

    float* out = (float*)d_out;
    float* comp_out  = out;                          // [B,T,D]
    float* recon_out = out + (size_t)BB * TT * DD;   // [B,L,D]

    float *pq, *pkv, *ptmp, *py;
    __nv_bfloat16 *pmh, *pml, *pqh, *pql, *pah, *pal, *pch, *pcl, *phh, *phl;
    __nv_bfloat16 *piwh, *piwl, *powh, *powl, *pw1h, *pw1l, *pw2h, *pw2l;
    cudaGetSymbolAddress((void**)&pq,   g_q);
    cudaGetSymbolAddress((void**)&pkv,  g_kv);
    cudaGetSymbolAddress((void**)&ptmp, g_tmp);
    cudaGetSymbolAddress((void**)&py,   g_y);
    cudaGetSymbolAddress((void**)&pmh,  g_mem_h);
    cudaGetSymbolAddress((void**)&pml,  g_mem_l);
    cudaGetSymbolAddress((void**)&pqh,  g_qry_h);
    cudaGetSymbolAddress((void**)&pql,  g_qry_l);
    cudaGetSymbolAddress((void**)&pah,  g_attn_h);
    cudaGetSymbolAddress((void**)&pal,  g_attn_l);
    cudaGetSymbolAddress((void**)&pch,  g_comp_h);
    cudaGetSymbolAddress((void**)&pcl,  g_comp_l);
    cudaGetSymbolAddress((void**)&phh,  g_h_h);
    cudaGetSymbolAddress((void**)&phl,  g_h_l);
    cudaGetSymbolAddress((void**)&piwh, g_inw_h);
    cudaGetSymbolAddress((void**)&piwl, g_inw_l);
    cudaGetSymbolAddress((void**)&powh, g_outw_h);
    cudaGetSymbolAddress((void**)&powl, g_outw_l);
    cudaGetSymbolAddress((void**)&pw1h, g_w1_h);
    cudaGetSymbolAddress((void**)&pw1l, g_w1_l);
    cudaGetSymbolAddress((void**)&pw2h, g_w2_h);
    cudaGetSymbolAddress((void**)&pw2l, g_w2_l);

    cudaFuncSetAttribute(gemm_mma_kernel,
                         cudaFuncAttributeMaxDynamicSharedMemorySize, GEMM_SMEM);

    // ---- pre-split fp32 -> bf16 hi/lo (4 launches so ncu -s 5 lands on GEMM2) ----
    {
        int n4 = (int)((size_t)BB * LL * DD / 4);
        split_kernel<<<(n4 + 255) / 256, 256>>>((const float4*)memory, (uint2*)pmh, (uint2*)pml, n4);   // #1
    }
    split_kernel<<<(3 * DD * DD / 4 + 255) / 256, 256>>>((const float4*)in_w, (uint2*)piwh, (uint2*)piwl, 3 * DD * DD / 4);  // #2
    split_kernel<<<(TT * DD / 4 + 255) / 256, 256>>>((const float4*)query, (uint2*)pqh, (uint2*)pql, TT * DD / 4);           // #3
    split3_kernel<<<(OW4 + W14 + W24 + 255) / 256, 256>>>(                                                                    // #4
        (const float4*)out_w, (uint2*)powh, (uint2*)powl,
        (const float4*)w1,    (uint2*)pw1h, (uint2*)pw1l,
        (const float4*)w2,    (uint2*)pw2h, (uint2*)pw2l);

    // 1) q = query @ Wq^T + bq             [64, 1024], K=1024          (#5)
    gemm_mma_kernel<<<dim3(8, 1), 256, GEMM_SMEM>>>(pqh, pql, piwh, piwl, in_b, pq, TT, DD, DD);

    // 2) KV = memory @ [Wk;Wv]^T + [bk;bv] [32768, 2048], K=1024       (#6 <- ncu captures this)
    gemm_mma_kernel<<<dim3(16, 256), 256, GEMM_SMEM>>>(pmh, pml,
                                                       piwh + (size_t)DD * DD, piwl + (size_t)DD * DD,
                                                       in_b + DD, pkv, BB * LL, D2, DD);

    // 3) flash attention -> attn bf16 hi/lo
    flash_attn_kernel<<<BB * HH, 256>>>(pq, pkv, pah, pal);

    // 4) out_proj: g_tmp = attn @ out_w^T + out_b  [512, 1024], K=1024
    gemm_mma_kernel<<<dim3(8, 4), 256, GEMM_SMEM>>>(pah, pal, powh, powl, out_b, ptmp,
                                                    BB * TT, DD, DD);

    // 5) LayerNorm -> compressed (d_out) + bf16 hi/lo planes
    ln_kernel<<<BB * TT, 256>>>(ptmp, lng, lnb, comp_out, (uint2*)pch, (uint2*)pcl);

    // 6) y = compressed @ w1^T + b1  [512, 2048], K=1024 (interp commutes with linear)
    gemm_mma_kernel<<<dim3(16, 4), 256, GEMM_SMEM>>>(pch, pcl, pw1h, pw1l, b1, py, BB * TT, D2, DD);

    // 7) h = gelu(interp(y)) -> bf16 hi/lo  [B,L,2048]
    interp_gelu_kernel<<<BB * LL, 256>>>(py, (uint2*)phh, (uint2*)phl);

    // 8) recon = h @ w2^T + b2  [32768, 1024], K=2048 -> d_out tail
    gemm_mma_kernel<<<dim3(8, 256), 256, GEMM_SMEM>>>(phh, phl, pw2h, pw2l, b2, recon_out,
                                                      BB * LL, DD, D2);
}

// round 17
// speedup vs baseline: 1.2313x; 1.2279x over previous
#include <cuda_runtime.h>
#include <cuda_fp16.h>
#include <math.h>
#include <stdint.h>

// Problem constants
#define BB 8
#define LL 4096
#define DD 1024
#define HH 16
#define HD 64
#define TT 64
#define D2 2048

// ---------------- scratch (device globals; no allocation) ----------------
__device__ float g_q[TT * DD];                          // projected query (fp32, attention input)
__device__ float g_kv[(size_t)BB * LL * D2];            // [B*L, 2048]: K | V (fp32)
__device__ float g_tmp[BB * TT * DD];                   // out_proj result (pre-LN)
__device__ float g_y[BB * TT * D2];                     // compressed @ w1^T + b1

// fp16 operand planes: activations get hi+lo (2-term), weights hi only
__device__ __half g_mem_h[(size_t)BB * LL * DD];
__device__ __half g_mem_l[(size_t)BB * LL * DD];
__device__ __half g_qry_h[TT * DD];
__device__ __half g_qry_l[TT * DD];
__device__ __half g_attn_h[BB * TT * DD];
__device__ __half g_attn_l[BB * TT * DD];
__device__ __half g_comp_h[BB * TT * DD];
__device__ __half g_comp_l[BB * TT * DD];
__device__ __half g_h_h[(size_t)BB * LL * D2];
__device__ __half g_h_l[(size_t)BB * LL * D2];
__device__ __half g_inw_h[3 * DD * DD];
__device__ __half g_outw_h[DD * DD];
__device__ __half g_w1_h[D2 * DD];
__device__ __half g_w2_h[DD * D2];

// ================= PTX primitives (baseline sm_80+, compiles for plain sm_103) =================
__device__ __forceinline__ uint32_t smem_u32(const void* p) {
    uint32_t a;
    asm("{ .reg .u64 t; cvta.to.shared.u64 t, %1; cvt.u32.u64 %0, t; }" : "=r"(a) : "l"(p));
    return a;
}
__device__ __forceinline__ void ldm_x4(uint32_t* r, uint32_t addr) {
    asm volatile("ldmatrix.sync.aligned.m8n8.x4.shared.b16 {%0,%1,%2,%3}, [%4];"
        : "=r"(r[0]), "=r"(r[1]), "=r"(r[2]), "=r"(r[3]) : "r"(addr));
}
__device__ __forceinline__ void mma_f16(float* d, const uint32_t* a, const uint32_t* b) {
    asm volatile("mma.sync.aligned.m16n8k16.row.col.f32.f16.f16.f32 "
        "{%0,%1,%2,%3}, {%4,%5,%6,%7}, {%8,%9}, {%0,%1,%2,%3};"
        : "+f"(d[0]), "+f"(d[1]), "+f"(d[2]), "+f"(d[3])
        : "r"(a[0]), "r"(a[1]), "r"(a[2]), "r"(a[3]), "r"(b[0]), "r"(b[1]));
}
__device__ __forceinline__ void cp16(uint32_t dst, const void* src) {
    asm volatile("cp.async.cg.shared.global [%0], [%1], 16;" :: "r"(dst), "l"(src));
}
__device__ __forceinline__ void cp16z(uint32_t dst, const void* src, int sz) {
    asm volatile("cp.async.cg.shared.global [%0], [%1], 16, %2;" :: "r"(dst), "l"(src), "r"(sz));
}
#define CP_COMMIT() asm volatile("cp.async.commit_group;" ::: "memory")
#define CP_WAIT1()  asm volatile("cp.async.wait_group 1;" ::: "memory")

// split one float4 into fp16 hi/lo pairs (each uint32 = 2 halves)
__device__ __forceinline__ void split_cvt(float4 v, uint2& hi, uint2& lo) {
    __half2 h01 = __floats2half2_rn(v.x, v.y);
    __half2 h23 = __floats2half2_rn(v.z, v.w);
    float2 f01 = __half22float2(h01);
    float2 f23 = __half22float2(h23);
    __half2 l01 = __floats2half2_rn(v.x - f01.x, v.y - f01.y);
    __half2 l23 = __floats2half2_rn(v.z - f23.x, v.w - f23.y);
    hi = make_uint2(*(uint32_t*)&h01, *(uint32_t*)&h23);
    lo = make_uint2(*(uint32_t*)&l01, *(uint32_t*)&l23);
}
__device__ __forceinline__ uint2 cvt_f16(float4 v) {
    __half2 h01 = __floats2half2_rn(v.x, v.y);
    __half2 h23 = __floats2half2_rn(v.z, v.w);
    return make_uint2(*(uint32_t*)&h01, *(uint32_t*)&h23);
}

// ---------------- fp32 -> fp16 hi/lo split (activations) ----------------
__global__ __launch_bounds__(256)
void split_kernel(const float4* __restrict__ x, uint2* __restrict__ hi,
                  uint2* __restrict__ lo, int n4) {
    int i = blockIdx.x * 256 + threadIdx.x;
    if (i < n4) {
        uint2 h, l;
        split_cvt(x[i], h, l);
        hi[i] = h;
        lo[i] = l;
    }
}

// ---------------- fp32 -> fp16 single-plane (weights) ----------------
__global__ __launch_bounds__(256)
void cvt_kernel(const float4* __restrict__ x, uint2* __restrict__ hi, int n4) {
    int i = blockIdx.x * 256 + threadIdx.x;
    if (i < n4) hi[i] = cvt_f16(x[i]);
}

// fused cvt for out_w + w1 + w2
#define OW4 (DD * DD / 4)
#define W14 (D2 * DD / 4)
#define W24 (DD * D2 / 4)
__global__ __launch_bounds__(256)
void cvt3_kernel(const float4* __restrict__ ow, uint2* __restrict__ owh,
                 const float4* __restrict__ w1, uint2* __restrict__ w1h,
                 const float4* __restrict__ w2, uint2* __restrict__ w2h) {
    int i = blockIdx.x * 256 + threadIdx.x;
    const float4* src; uint2* dh; int j;
    if (i < OW4)                  { src = ow; dh = owh; j = i; }
    else if (i < OW4 + W14)       { src = w1; dh = w1h; j = i - OW4; }
    else if (i < OW4 + W14 + W24) { src = w2; dh = w2h; j = i - OW4 - W14; }
    else return;
    dh[j] = cvt_f16(src[j]);
}

// ============ warp-MMA GEMM: C[M,N] = A[M,K] @ W[N,K]^T + bias[N] ============
// A as fp16 hi/lo planes (2-term), W as single fp16 plane.
// 2-term product (ah*bh + al*bh), fp32 accum -> rel err ~3e-4 (fp16 round 2^-11,
// sign-independent over K -> RMS ~2^-11/sqrt(3)).
// 128x128 tile / CTA, 8 warps, warp tile 64x32. cp.async 3-stage pipeline, K-slab 32.
// Term-major MMA issue (16 independent accs between chain links).
// N % 128 == 0, K % 32 == 0, nslab >= 2; M ragged (zfill + guarded epilogue).
#define KSLAB 32
#define SROWB 80                       // bytes per smem row (40 halves) -> conflict-free ldmatrix
#define PLANE_B (128 * SROWB)          // 10240
#define STAGE_B (3 * PLANE_B)          // Ahi, Alo, Bhi = 30720
#define STAGES 3
#define GEMM_SMEM (STAGES * STAGE_B)   // 92160

__device__ __forceinline__ void issue_slab(
    uint32_t sbase,
    const __half* __restrict__ Ah, const __half* __restrict__ Al,
    const __half* __restrict__ Wh,
    int row0, int col0, int M, int K, int k0, int tid) {
    const int r = tid >> 2;            // 0..63
    const int q = tid & 3;             // 16B chunk within 32-col slab
    #pragma unroll
    for (int i = 0; i < 2; i++) {
        const int rr = r + 64 * i;
        const uint32_t off = (uint32_t)(rr * SROWB + q * 16);
        const size_t aoff = (size_t)(row0 + rr) * K + k0 + q * 8;
        const int asz = (row0 + rr < M) ? 16 : 0;
        cp16z(sbase + off,               Ah + aoff, asz);
        cp16z(sbase + PLANE_B + off,     Al + aoff, asz);
        const size_t boff = (size_t)(col0 + rr) * K + k0 + q * 8;
        cp16(sbase + 2 * PLANE_B + off,  Wh + boff);
    }
}

__global__ __launch_bounds__(256, 1)
void gemm_mma_kernel(const __half* __restrict__ Ah, const __half* __restrict__ Al,
                     const __half* __restrict__ Wh,
                     const float* __restrict__ bias, float* __restrict__ C,
                     int M, int N, int K) {
    extern __shared__ char sm[];
    const uint32_t sb = smem_u32(sm);

    const int tid    = threadIdx.x;
    const int wid    = tid >> 5;
    const int lane   = tid & 31;
    const int warp_m = wid & 1;        // 0..1 -> 64-row halves
    const int warp_n = wid >> 1;       // 0..3 -> 32-col quarters
    const int row0   = blockIdx.y * 128;
    const int col0   = blockIdx.x * 128;

    float c[4][4][4];
    #pragma unroll
    for (int i = 0; i < 4; i++)
        #pragma unroll
        for (int j = 0; j < 4; j++)
            #pragma unroll
            for (int t = 0; t < 4; t++) c[i][j][t] = 0.f;

    const int nslab = K / KSLAB;

    // prologue: stages 0,1 in flight
    issue_slab(sb,           Ah, Al, Wh, row0, col0, M, K, 0,      tid);
    CP_COMMIT();
    issue_slab(sb + STAGE_B, Ah, Al, Wh, row0, col0, M, K, KSLAB, tid);
    CP_COMMIT();

    for (int s = 0; s < nslab; s++) {
        CP_WAIT1();                    // slab s resident (s+1 may still fly)
        __syncthreads();               // all warps past compute of s-1; its buffer is free

        if (s + 2 < nslab)
            issue_slab(sb + ((s + 2) % STAGES) * STAGE_B, Ah, Al, Wh,
                       row0, col0, M, K, (s + 2) * KSLAB, tid);
        CP_COMMIT();                   // always commit to keep group accounting uniform

        const uint32_t bbase = sb + (s % STAGES) * STAGE_B;

        #pragma unroll
        for (int ks = 0; ks < 2; ks++) {
            uint32_t ah[4][4], al[4][4], bh[2][4];
            const int arow = warp_m * 64 + (lane & 15);
            const int akh  = lane >> 4;
            #pragma unroll
            for (int ma = 0; ma < 4; ma++) {
                uint32_t addr = bbase + (uint32_t)((arow + ma * 16) * SROWB + ks * 32 + akh * 16);
                ldm_x4(ah[ma], addr);
                ldm_x4(al[ma], addr + PLANE_B);
            }
            // B: W is [N,K] (K contig) == col-major B for mma.row.col -> NON-trans ldmatrix.
            const int bn  = warp_n * 32 + (lane & 7) + ((lane >> 4) << 3);
            const int bkh = (lane >> 3) & 1;
            #pragma unroll
            for (int p = 0; p < 2; p++) {
                uint32_t addr = bbase + 2 * PLANE_B
                              + (uint32_t)((bn + p * 16) * SROWB + ks * 32 + bkh * 16);
                ldm_x4(bh[p], addr);
            }
            // Term-major: hh pass then lh pass (16 independent accs between links).
            #pragma unroll
            for (int ma = 0; ma < 4; ma++)
                #pragma unroll
                for (int na = 0; na < 4; na++)
                    mma_f16(c[ma][na], ah[ma], &bh[na >> 1][(na & 1) * 2]);   // hi*hi
            #pragma unroll
            for (int ma = 0; ma < 4; ma++)
                #pragma unroll
                for (int na = 0; na < 4; na++)
                    mma_f16(c[ma][na], al[ma], &bh[na >> 1][(na & 1) * 2]);   // lo*hi
        }
    }

    // epilogue: fragment -> gmem with bias
    const int g  = lane >> 2;
    const int tg = lane & 3;
    #pragma unroll
    for (int ma = 0; ma < 4; ma++) {
        #pragma unroll
        for (int half = 0; half < 2; half++) {
            int r = row0 + warp_m * 64 + ma * 16 + g + half * 8;
            if (r < M) {
                float* cp = C + (size_t)r * N;
                #pragma unroll
                for (int na = 0; na < 4; na++) {
                    int cc = col0 + warp_n * 32 + na * 8 + tg * 2;
                    float2 o;
                    o.x = c[ma][na][half * 2 + 0] + bias[cc + 0];
                    o.y = c[ma][na][half * 2 + 1] + bias[cc + 1];
                    *(float2*)(cp + cc) = o;
                }
            }
        }
    }
}

// ---------------- flash attention: one CTA per (b,h); writes fp16 hi/lo ----------------
__global__ __launch_bounds__(256)
void flash_attn_kernel(const float* __restrict__ q, const float* __restrict__ kv,
                       __half* __restrict__ attn_h, __half* __restrict__ attn_l) {
    const int bh = blockIdx.x;
    const int b = bh / HH, h = bh % HH;

    __shared__ float Qs[64][68];
    __shared__ float Ks[32][68];
    __shared__ float Vs[32][68];
    __shared__ float Ps[64][36];

    const int tid = threadIdx.x;
    const int tx = tid & 7;
    const int ty = tid >> 3;
    const int t0 = ty * 2, t1 = t0 + 1;

    {
        int r = tid >> 2;
        int cc = (tid & 3) * 16;
        const float* src = q + (size_t)r * DD + h * HD + cc;
        *(float4*)&Qs[r][cc]      = *(const float4*)(src);
        *(float4*)&Qs[r][cc + 4]  = *(const float4*)(src + 4);
        *(float4*)&Qs[r][cc + 8]  = *(const float4*)(src + 8);
        *(float4*)&Qs[r][cc + 12] = *(const float4*)(src + 12);
    }

    float m0 = -3.402823466e38f, m1 = -3.402823466e38f;
    float l0s = 0.f, l1s = 0.f;
    float o0[8], o1[8];
    #pragma unroll
    for (int j = 0; j < 8; j++) { o0[j] = 0.f; o1[j] = 0.f; }

    for (int lb = 0; lb < LL; lb += 32) {
        {
            int r = tid >> 3;
            int cc = (tid & 7) * 8;
            const float* kp = kv + (size_t)(b * LL + lb + r) * D2 + h * HD + cc;
            *(float4*)&Ks[r][cc]     = *(const float4*)kp;
            *(float4*)&Ks[r][cc + 4] = *(const float4*)(kp + 4);
            const float* vp = kp + DD;
            *(float4*)&Vs[r][cc]     = *(const float4*)vp;
            *(float4*)&Vs[r][cc + 4] = *(const float4*)(vp + 4);
        }
        __syncthreads();

        float s0[4] = {0.f, 0.f, 0.f, 0.f};
        float s1[4] = {0.f, 0.f, 0.f, 0.f};
        #pragma unroll 8
        for (int d = 0; d < 64; d++) {
            float a0 = Qs[t0][d];
            float a1 = Qs[t1][d];
            #pragma unroll
            for (int j = 0; j < 4; j++) {
                float kk = Ks[tx * 4 + j][d];
                s0[j] = fmaf(a0, kk, s0[j]);
                s1[j] = fmaf(a1, kk, s1[j]);
            }
        }
        #pragma unroll
        for (int j = 0; j < 4; j++) { s0[j] *= 0.125f; s1[j] *= 0.125f; }

        float rm0 = fmaxf(fmaxf(s0[0], s0[1]), fmaxf(s0[2], s0[3]));
        float rm1 = fmaxf(fmaxf(s1[0], s1[1]), fmaxf(s1[2], s1[3]));
        #pragma unroll
        for (int off = 1; off < 8; off <<= 1) {
            rm0 = fmaxf(rm0, __shfl_xor_sync(0xffffffffu, rm0, off));
            rm1 = fmaxf(rm1, __shfl_xor_sync(0xffffffffu, rm1, off));
        }
        float mn0 = fmaxf(m0, rm0), mn1 = fmaxf(m1, rm1);
        float c0 = __expf(m0 - mn0), c1 = __expf(m1 - mn1);

        float p0[4], p1[4];
        float rs0 = 0.f, rs1 = 0.f;
        #pragma unroll
        for (int j = 0; j < 4; j++) {
            p0[j] = __expf(s0[j] - mn0); rs0 += p0[j];
            p1[j] = __expf(s1[j] - mn1); rs1 += p1[j];
        }
        #pragma unroll
        for (int off = 1; off < 8; off <<= 1) {
            rs0 += __shfl_xor_sync(0xffffffffu, rs0, off);
            rs1 += __shfl_xor_sync(0xffffffffu, rs1, off);
        }
        l0s = l0s * c0 + rs0;
        l1s = l1s * c1 + rs1;
        m0 = mn0; m1 = mn1;
        #pragma unroll
        for (int j = 0; j < 8; j++) { o0[j] *= c0; o1[j] *= c1; }

        #pragma unroll
        for (int j = 0; j < 4; j++) {
            Ps[t0][tx * 4 + j] = p0[j];
            Ps[t1][tx * 4 + j] = p1[j];
        }
        __syncthreads();

        #pragma unroll 4
        for (int lc = 0; lc < 32; lc++) {
            float pv0 = Ps[t0][lc];
            float pv1 = Ps[t1][lc];
            #pragma unroll
            for (int j = 0; j < 8; j++) {
                float vv = Vs[lc][tx * 8 + j];
                o0[j] = fmaf(pv0, vv, o0[j]);
                o1[j] = fmaf(pv1, vv, o1[j]);
            }
        }
        __syncthreads();
    }

    float inv0 = 1.f / l0s, inv1 = 1.f / l1s;
    size_t base0 = (size_t)(b * TT + t0) * DD + h * HD + tx * 8;
    size_t base1 = (size_t)(b * TT + t1) * DD + h * HD + tx * 8;
    #pragma unroll
    for (int j = 0; j < 8; j++) {
        float v0 = o0[j] * inv0;
        float v1 = o1[j] * inv1;
        __half h0 = __float2half_rn(v0);
        __half h1 = __float2half_rn(v1);
        attn_h[base0 + j] = h0;
        attn_l[base0 + j] = __float2half_rn(v0 - __half2float(h0));
        attn_h[base1 + j] = h1;
        attn_l[base1 + j] = __float2half_rn(v1 - __half2float(h1));
    }
}

// ---------------- LayerNorm (1024) -> fp32 out + fp16 hi/lo planes ----------------
__global__ __launch_bounds__(256)
void ln_kernel(const float* __restrict__ x, const float* __restrict__ gam,
               const float* __restrict__ bet, float* __restrict__ out,
               uint2* __restrict__ comp_h, uint2* __restrict__ comp_l) {
    const int row = blockIdx.x;
    const int tid = threadIdx.x;
    const float4* xr = (const float4*)(x + (size_t)row * DD);
    float4 v = xr[tid];
    float s  = v.x + v.y + v.z + v.w;
    float sq = v.x * v.x + v.y * v.y + v.z * v.z + v.w * v.w;
    #pragma unroll
    for (int off = 16; off > 0; off >>= 1) {
        s  += __shfl_xor_sync(0xffffffffu, s, off);
        sq += __shfl_xor_sync(0xffffffffu, sq, off);
    }
    __shared__ float ss[8], ssq[8];
    int w = tid >> 5, ln = tid & 31;
    if (ln == 0) { ss[w] = s; ssq[w] = sq; }
    __syncthreads();
    if (tid < 32) {
        float a = (tid < 8) ? ss[tid] : 0.f;
        float bq = (tid < 8) ? ssq[tid] : 0.f;
        #pragma unroll
        for (int off = 4; off > 0; off >>= 1) {
            a  += __shfl_xor_sync(0xffffffffu, a, off);
            bq += __shfl_xor_sync(0xffffffffu, bq, off);
        }
        if (tid == 0) { ss[0] = a; ssq[0] = bq; }
    }
    __syncthreads();
    float mu  = ss[0] * (1.f / 1024.f);
    float var = ssq[0] * (1.f / 1024.f) - mu * mu;
    float rstd = rsqrtf(var + 1e-5f);
    float4 gg = ((const float4*)gam)[tid];
    float4 bb = ((const float4*)bet)[tid];
    float4 o;
    o.x = (v.x - mu) * rstd * gg.x + bb.x;
    o.y = (v.y - mu) * rstd * gg.y + bb.y;
    o.z = (v.z - mu) * rstd * gg.z + bb.z;
    o.w = (v.w - mu) * rstd * gg.w + bb.w;
    ((float4*)(out + (size_t)row * DD))[tid] = o;
    uint2 hi, lo;
    split_cvt(o, hi, lo);
    comp_h[(size_t)row * (DD / 4) + tid] = hi;
    comp_l[(size_t)row * (DD / 4) + tid] = lo;
}

// ---------------- interp(y, T->L) + exact GELU -> fp16 hi/lo planes ----------------
__device__ __forceinline__ float gelu_exact(float x) {
    return 0.5f * x * (1.f + erff(x * 0.70710678118654752f));
}

__global__ __launch_bounds__(256)
void interp_gelu_kernel(const float* __restrict__ y,
                        uint2* __restrict__ h_h, uint2* __restrict__ h_l) {
    const int bl = blockIdx.x;
    const int b = bl >> 12;
    const int l = bl & 4095;
    float pos = ((float)l + 0.5f) * (64.f / 4096.f) - 0.5f;
    pos = fminf(fmaxf(pos, 0.f), 63.f);
    int i0 = (int)floorf(pos);
    int i1 = min(i0 + 1, 63);
    float f = pos - (float)i0;

    const float4* y0 = (const float4*)(y + (size_t)(b * TT + i0) * D2);
    const float4* y1 = (const float4*)(y + (size_t)(b * TT + i1) * D2);
    const size_t rowbase = (size_t)bl * (D2 / 4);
    const int tid = threadIdx.x;
    #pragma unroll
    for (int i = 0; i < 2; i++) {
        int idx = tid + i * 256;
        float4 a = y0[idx];
        float4 cv = y1[idx];
        float4 r;
        r.x = gelu_exact(a.x + f * (cv.x - a.x));
        r.y = gelu_exact(a.y + f * (cv.y - a.y));
        r.z = gelu_exact(a.z + f * (cv.z - a.z));
        r.w = gelu_exact(a.w + f * (cv.w - a.w));
        uint2 hi, lo;
        split_cvt(r, hi, lo);
        h_h[rowbase + idx] = hi;
        h_l[rowbase + idx] = lo;
    }
}

// ---------------- launch ----------------
extern "C" void kernel_launch(void* const* d_in, const int* in_sizes, int n_in,
                              void* d_out, int out_size) {
    const float* memory  = (const float*)d_in[0];   // [B,L,D]
    const float* query   = (const float*)d_in[1];   // [1,T,D]
    const float* in_w    = (const float*)d_in[2];   // [3D,D]
    const float* in_b    = (const float*)d_in[3];   // [3D]
    const float* out_w   = (const float*)d_in[4];   // [D,D]
    const float* out_b   = (const float*)d_in[5];   // [D]
    const float* lng     = (const float*)d_in[6];   // [D]
    const float* lnb     = (const float*)d_in[7];   // [D]
    const float* w1      = (const float*)d_in[8];   // [2D,D]
    const float* b1      = (const float*)d_in[9];   // [2D]
    const float* w2      = (const float*)d_in[10];  // [D,2D]
    const float* b2      = (const float*)d_in[11];  // [D]

    float* out = (float*)d_out;
    float* comp_out  = out;                          // [B,T,D]
    float* recon_out = out + (size_t)BB * TT * DD;   // [B,L,D]

    float *pq, *pkv, *ptmp, *py;
    __half *pmh, *pml, *pqh, *pql, *pah, *pal, *pch, *pcl, *phh, *phl;
    __half *piwh, *powh, *pw1h, *pw2h;
    cudaGetSymbolAddress((void**)&pq,   g_q);
    cudaGetSymbolAddress((void**)&pkv,  g_kv);
    cudaGetSymbolAddress((void**)&ptmp, g_tmp);
    cudaGetSymbolAddress((void**)&py,   g_y);
    cudaGetSymbolAddress((void**)&pmh,  g_mem_h);
    cudaGetSymbolAddress((void**)&pml,  g_mem_l);
    cudaGetSymbolAddress((void**)&pqh,  g_qry_h);
    cudaGetSymbolAddress((void**)&pql,  g_qry_l);
    cudaGetSymbolAddress((void**)&pah,  g_attn_h);
    cudaGetSymbolAddress((void**)&pal,  g_attn_l);
    cudaGetSymbolAddress((void**)&pch,  g_comp_h);
    cudaGetSymbolAddress((void**)&pcl,  g_comp_l);
    cudaGetSymbolAddress((void**)&phh,  g_h_h);
    cudaGetSymbolAddress((void**)&phl,  g_h_l);
    cudaGetSymbolAddress((void**)&piwh, g_inw_h);
    cudaGetSymbolAddress((void**)&powh, g_outw_h);
    cudaGetSymbolAddress((void**)&pw1h, g_w1_h);
    cudaGetSymbolAddress((void**)&pw2h, g_w2_h);

    cudaFuncSetAttribute(gemm_mma_kernel,
                         cudaFuncAttributeMaxDynamicSharedMemorySize, GEMM_SMEM);

    // ---- pre-pass (4 launches so ncu -s 5 lands on GEMM2 at #6) ----
    {
        int n4 = (int)((size_t)BB * LL * DD / 4);
        split_kernel<<<(n4 + 255) / 256, 256>>>((const float4*)memory, (uint2*)pmh, (uint2*)pml, n4);   // #1
    }
    cvt_kernel<<<(3 * DD * DD / 4 + 255) / 256, 256>>>((const float4*)in_w, (uint2*)piwh, 3 * DD * DD / 4);  // #2
    split_kernel<<<(TT * DD / 4 + 255) / 256, 256>>>((const float4*)query, (uint2*)pqh, (uint2*)pql, TT * DD / 4);  // #3
    cvt3_kernel<<<(OW4 + W14 + W24 + 255) / 256, 256>>>(                                                  // #4
        (const float4*)out_w, (uint2*)powh,
        (const float4*)w1,    (uint2*)pw1h,
        (const float4*)w2,    (uint2*)pw2h);

    // 1) q = query @ Wq^T + bq             [64, 1024], K=1024          (#5)
    gemm_mma_kernel<<<dim3(8, 1), 256, GEMM_SMEM>>>(pqh, pql, piwh, in_b, pq, TT, DD, DD);

    // 2) KV = memory @ [Wk;Wv]^T + [bk;bv] [32768, 2048], K=1024       (#6 <- ncu captures this)
    gemm_mma_kernel<<<dim3(16, 256), 256, GEMM_SMEM>>>(pmh, pml, piwh + (size_t)DD * DD,
                                                       in_b + DD, pkv, BB * LL, D2, DD);

    // 3) flash attention -> attn fp16 hi/lo
    flash_attn_kernel<<<BB * HH, 256>>>(pq, pkv, pah, pal);

    // 4) out_proj: g_tmp = attn @ out_w^T + out_b  [512, 1024], K=1024
    gemm_mma_kernel<<<dim3(8, 4), 256, GEMM_SMEM>>>(pah, pal, powh, out_b, ptmp,
                                                    BB * TT, DD, DD);

    // 5) LayerNorm -> compressed (d_out) + fp16 hi/lo planes
    ln_kernel<<<BB * TT, 256>>>(ptmp, lng, lnb, comp_out, (uint2*)pch, (uint2*)pcl);

    // 6) y = compressed @ w1^T + b1  [512, 2048], K=1024 (interp commutes with linear)
    gemm_mma_kernel<<<dim3(16, 4), 256, GEMM_SMEM>>>(pch, pcl, pw1h, b1, py, BB * TT, D2, DD);

    // 7) h = gelu(interp(y)) -> fp16 hi/lo  [B,L,2048]
    interp_gelu_kernel<<<BB * LL, 256>>>(py, (uint2*)phh, (uint2*)phl);

    // 8) recon = h @ w2^T + b2  [32768, 1024], K=2048 -> d_out tail
    gemm_mma_kernel<<<dim3(8, 256), 256, GEMM_SMEM>>>(phh, phl, pw2h, b2, recon_out,
                                                      BB * LL, DD, D2);
}